// round 1
// baseline (speedup 1.0000x reference)
#include <cuda_runtime.h>
#include <math.h>

#define DPI 3.14159265358979323846

// ---- problem dims ----
#define NB   128
#define NIN  30     // 2*B_IN
#define BB1  10
#define MM1  19     // 2*B1-1
#define NA1  20     // 2*B1
#define FF1  20
#define BB2  6
#define MM2  11     // 2*B2-1
#define NA2  12     // 2*B2
#define FF2  40
#define FOUT 10
#define P1   24
#define P2   144

// ---- constant tables (rebuilt on device every call) ----
__device__ float  gWS2F[BB1*MM1*NIN];              // [l][m][k]
__device__ float2 gT1[BB1*MM1*NIN*NIN];            // [l][m][k*30+j]
__device__ float2 gBS2[P1*BB1*MM1];                // [p][l][m]
__device__ float  gWINV1[NA1*BB1*MM1*MM1];         // [k][l][m][n]
__device__ float2 gEA1[MM1*NA1];                   // [m][a]  exp(+i(m-9)*2pi*a/20)
__device__ float  gWSO3[NA1*BB2*MM2*MM2];          // [k][l][m][n]
__device__ float2 gF20[MM2*NA1];                   // [mu][a] exp(-2pi i (mu-5) a /20)
__device__ float2 gBSO3[P2*BB2*MM2*MM2];           // [p][l][m][n]
__device__ float  gWINV2[NA2*BB2*MM2*MM2];         // [k][l][m][n]
__device__ float2 gEA2[MM2*NA2];                   // [m][a]  exp(+i(m-5)*2pi*a/12)
__device__ float  gWINT[NA2];

// ---- scratch ----
__device__ float2 gX   [NB*BB1*MM1];
__device__ float2 gPSI [FF1*BB1*MM1];
__device__ float2 gFH  [NB*FF1*NA1*MM1*MM1];       // 18,483,200
__device__ float2 gT   [NB*FF1*NA1*MM1*NA1];       // 19,456,000
__device__ float  gY   [NB*FF1*NA1*NA1*NA1];       // 20,480,000
__device__ float2 gU   [NB*FF1*NA1*MM2*NA1];       // 11,264,000
__device__ float2 gYMN [NB*FF1*NA1*MM2*MM2];       //  6,195,200
__device__ float2 gX2  [NB*FF1*BB2*MM2*MM2];       //  1,858,560
__device__ float2 gPSI2[FF1*FF2*BB2*MM2*MM2];      //    580,800
__device__ float2 gZ2  [NB*FF2*BB2*MM2*MM2];       //  3,717,120
__device__ float2 gFH2 [NB*FF2*NA2*MM2*MM2];       //  7,434,240
__device__ float2 gT2  [NB*FF2*NA2*MM2*NA2];       //  8,110,080
__device__ float  gY2  [NB*FF2*NA2*NA2*NA2];       //  8,847,360
__device__ float  gFEAT[NB*FF2];

// ---- exact factorials 0..20 (match python float(factorial(n))) ----
__device__ __constant__ double c_fact[21] = {
  1.0, 1.0, 2.0, 6.0, 24.0, 120.0, 720.0, 5040.0, 40320.0, 362880.0,
  3628800.0, 39916800.0, 479001600.0, 6227020800.0, 87178291200.0,
  1307674368000.0, 20922789888000.0, 355687428096000.0,
  6402373705728000.0, 121645100408832000.0, 2432902008176640000.0 };

__device__ __forceinline__ double ipowd(double x, int e) {
  double r = 1.0;
  for (int i = 0; i < e; ++i) r *= x;
  return r;
}

// Wigner small-d, m,n in [-l,l]
__device__ double wigd(int l, int m, int n, double beta) {
  double cb = cos(0.5 * beta), sb = sin(0.5 * beta);
  double pref = sqrt(c_fact[l+m] * c_fact[l-m] * c_fact[l+n] * c_fact[l-n]);
  int s0 = (n - m > 0) ? (n - m) : 0;
  int s1 = (l + n < l - m) ? (l + n) : (l - m);
  double v = 0.0;
  for (int s = s0; s <= s1; ++s) {
    double t = 1.0 / (c_fact[l+n-s] * c_fact[s] * c_fact[m-n+s] * c_fact[l-m-s]);
    if ((m - n + s) & 1) t = -t;
    v += t * ipowd(cb, 2*l + n - m - 2*s) * ipowd(sb, m - n + 2*s);
  }
  return pref * v;
}

__device__ double quadw(int b, int k) {
  double beta = DPI * (2*k + 1) / (4.0 * b);
  double s = 0.0;
  for (int j = 0; j < b; ++j) s += sin((2*j + 1) * beta) / (2*j + 1);
  return 2.0 / b * sin(beta) * s;
}

// ======================= init kernels =======================
__global__ void k_init_small() {
  const int TOT = 5700 + 4560 + 72200 + 380 + 14520 + 220 + 104544 + 8712 + 132 + 12;
  for (int idx = blockIdx.x * blockDim.x + threadIdx.x; idx < TOT;
       idx += gridDim.x * blockDim.x) {
    int r = idx;
    if (r < 5700) {  // WS2F [l][m][k] : Wigner col n=0 * quad weight
      int l = r / 570, m = (r / 30) % 19, k = r % 30;
      int mp = m - 9;
      double w = 0.0;
      if (abs(mp) <= l) {
        double beta = DPI * (2*k + 1) / 60.0;
        w = wigd(l, mp, 0, beta) * quadw(15, k);
      }
      gWS2F[r] = (float)w; continue;
    }
    r -= 5700;
    if (r < 4560) {  // BS2 [p][l][m]
      int p = r / 190, l = (r / 19) % 10, m = r % 19, mp = m - 9;
      float2 v = make_float2(0.f, 0.f);
      if (abs(mp) <= l) {
        int ib = p / 8, ia = p % 8;
        double beta = (ib + 1) * DPI / 24.0;
        double d = wigd(l, mp, 0, beta);
        double ph = -(double)mp * (2.0 * DPI * ia / 8.0);
        double s, c; sincos(ph, &s, &c);
        v = make_float2((float)(d * c), (float)(d * s));
      }
      gBS2[r] = v; continue;
    }
    r -= 4560;
    if (r < 72200) {  // WINV1 [k][l][m][n]
      int k = r / 3610, l = (r / 361) % 10, m = (r / 19) % 19, n = r % 19;
      int mp = m - 9, np = n - 9;
      double w = 0.0;
      if (abs(mp) <= l && abs(np) <= l) {
        double beta = DPI * (2*k + 1) / 40.0;
        w = wigd(l, mp, np, beta) * (2*l + 1);
      }
      gWINV1[r] = (float)w; continue;
    }
    r -= 72200;
    if (r < 380) {  // EA1 [m][a]
      int m = r / 20, a = r % 20;
      double ph = (double)(m - 9) * 2.0 * DPI * a / 20.0;
      double s, c; sincos(ph, &s, &c);
      gEA1[r] = make_float2((float)c, (float)s); continue;
    }
    r -= 380;
    if (r < 14520) {  // WSO3 [k][l][m][n]
      int k = r / 726, l = (r / 121) % 6, m = (r / 11) % 11, n = r % 11;
      int mp = m - 5, np = n - 5;
      double w = 0.0;
      if (abs(mp) <= l && abs(np) <= l) {
        double beta = DPI * (2*k + 1) / 40.0;
        w = wigd(l, mp, np, beta) * quadw(10, k);
      }
      gWSO3[r] = (float)w; continue;
    }
    r -= 14520;
    if (r < 220) {  // F20 [mu][a]
      int mu = r / 20, a = r % 20;
      double ph = -2.0 * DPI * (double)(mu - 5) * a / 20.0;
      double s, c; sincos(ph, &s, &c);
      gF20[r] = make_float2((float)c, (float)s); continue;
    }
    r -= 220;
    if (r < 104544) {  // BSO3 [p][l][m][n]
      int p = r / 726, l = (r / 121) % 6, m = (r / 11) % 11, n = r % 11;
      int mp = m - 5, np = n - 5;
      float2 v = make_float2(0.f, 0.f);
      if (abs(mp) <= l && abs(np) <= l) {
        int ib = p / 48, ia = (p / 6) % 8, ig = p % 6;
        double beta = (ib + 1) * DPI / 24.0;
        double d = wigd(l, mp, np, beta);
        double ph = -((double)mp * (2.0 * DPI * ia / 8.0) +
                      (double)np * (2.0 * DPI * ig / 6.0));
        double s, c; sincos(ph, &s, &c);
        v = make_float2((float)(d * c), (float)(d * s));
      }
      gBSO3[r] = v; continue;
    }
    r -= 104544;
    if (r < 8712) {  // WINV2 [k][l][m][n]
      int k = r / 726, l = (r / 121) % 6, m = (r / 11) % 11, n = r % 11;
      int mp = m - 5, np = n - 5;
      double w = 0.0;
      if (abs(mp) <= l && abs(np) <= l) {
        double beta = DPI * (2*k + 1) / 24.0;
        w = wigd(l, mp, np, beta) * (2*l + 1);
      }
      gWINV2[r] = (float)w; continue;
    }
    r -= 8712;
    if (r < 132) {  // EA2 [m][a]
      int m = r / 12, a = r % 12;
      double ph = (double)(m - 5) * 2.0 * DPI * a / 12.0;
      double s, c; sincos(ph, &s, &c);
      gEA2[r] = make_float2((float)c, (float)s); continue;
    }
    r -= 132;
    gWINT[r] = (float)quadw(6, r);
  }
}

__global__ void k_init_T1() {  // T1[l][m][k*30+j] = WS2F[l][m][k]*exp(-2pi i (m-9) j /30)
  int idx = blockIdx.x * blockDim.x + threadIdx.x;
  if (idx >= BB1*MM1*900) return;
  int lm = idx / 900, kj = idx % 900;
  int k = kj / 30, j = kj % 30;
  int mp = (lm % 19) - 9;
  float w = gWS2F[lm * 30 + k];
  double ph = -2.0 * DPI * (double)mp * j / 30.0;
  double s, c; sincos(ph, &s, &c);
  gT1[idx] = make_float2((float)(w * c), (float)(w * s));
}

// ======================= pipeline kernels =======================
// X[b,l,m] = sum_{k,j} T1[l,m,k,j] * x[b,k,j]
__global__ void k_x(const float* __restrict__ x) {
  __shared__ float xs[900];
  int b = blockIdx.x;
  for (int i = threadIdx.x; i < 900; i += blockDim.x) xs[i] = x[b*900 + i];
  __syncthreads();
  int t = threadIdx.x;
  if (t < BB1*MM1) {
    const float2* T = &gT1[t * 900];
    float re = 0.f, im = 0.f;
    for (int i = 0; i < 900; ++i) {
      float xv = xs[i]; float2 w = T[i];
      re += xv * w.x; im += xv * w.y;
    }
    gX[b * 190 + t] = make_float2(re, im);
  }
}

// psi[o,l,m] = sum_p kernel1[o,p] * BS2[p,l,m]
__global__ void k_psi(const float* __restrict__ k1) {
  int idx = blockIdx.x * blockDim.x + threadIdx.x;
  if (idx >= FF1*BB1*MM1) return;
  int lm = idx % 190, o = idx / 190;
  float re = 0.f, im = 0.f;
  for (int p = 0; p < P1; ++p) {
    float kv = k1[o*P1 + p];
    float2 bv = gBS2[p*190 + lm];
    re += kv * bv.x; im += kv * bv.y;
  }
  gPSI[idx] = make_float2(re, im);
}

// fh[b,o,k,m,n] = sum_l WINV1[k,l,m,n] * X[b,l,m] * conj(psi[o,l,n])
__global__ void k_fh() {
  int idx = blockIdx.x * blockDim.x + threadIdx.x;
  if (idx >= NB*FF1*NA1*MM1*MM1) return;
  int n = idx % 19, m = (idx / 19) % 19, k = (idx / 361) % 20;
  int o = (idx / 7220) % 20, b = idx / 144400;
  float re = 0.f, im = 0.f;
#pragma unroll
  for (int l = 0; l < BB1; ++l) {
    float w = gWINV1[(k*BB1 + l)*361 + m*19 + n];
    float2 xm = gX[(b*BB1 + l)*19 + m];
    float2 pe = gPSI[(o*BB1 + l)*19 + n];
    re += w * (xm.x * pe.x + xm.y * pe.y);
    im += w * (xm.y * pe.x - xm.x * pe.y);
  }
  gFH[idx] = make_float2(re, im);
}

// t[b,o,k,m,g] = sum_n fh[b,o,k,m,n] * EA1[n,g]
__global__ void k_t() {
  int idx = blockIdx.x * blockDim.x + threadIdx.x;
  if (idx >= NB*FF1*NA1*MM1) return;
  long base = (long)idx * 19;
  float2 f[19];
#pragma unroll
  for (int n = 0; n < 19; ++n) f[n] = gFH[base + n];
  long tb = (long)idx * 20;
  for (int g = 0; g < 20; ++g) {
    float re = 0.f, im = 0.f;
#pragma unroll
    for (int n = 0; n < 19; ++n) {
      float2 e = gEA1[n*20 + g];
      re += f[n].x * e.x - f[n].y * e.y;
      im += f[n].x * e.y + f[n].y * e.x;
    }
    gT[tb + g] = make_float2(re, im);
  }
}

// y[b,o,k,a,g] = relu(Re(sum_m t[b,o,k,m,g] * EA1[m,a]))
__global__ void k_y() {
  int idx = blockIdx.x * blockDim.x + threadIdx.x;
  if (idx >= NB*FF1*NA1*NA1) return;
  int g = idx % 20, bok = idx / 20;
  long tbase = (long)bok * 380 + g;
  float2 tm[19];
#pragma unroll
  for (int m = 0; m < 19; ++m) tm[m] = gT[tbase + m*20];
  long yb = (long)bok * 400 + g;
  for (int a = 0; a < 20; ++a) {
    float v = 0.f;
#pragma unroll
    for (int m = 0; m < 19; ++m) {
      float2 e = gEA1[m*20 + a];
      v += tm[m].x * e.x - tm[m].y * e.y;
    }
    gY[yb + a*20] = (v > 0.f) ? v : 0.f;
  }
}

// u[b,c,k,mu,g] = sum_a y[b,c,k,a,g] * F20[mu,a]
__global__ void k_u() {
  int idx = blockIdx.x * blockDim.x + threadIdx.x;
  if (idx >= NB*FF1*NA1*NA1) return;
  int g = idx % 20, bck = idx / 20;
  long ybase = (long)bck * 400 + g;
  float ya[20];
#pragma unroll
  for (int a = 0; a < 20; ++a) ya[a] = gY[ybase + a*20];
  long ub = (long)bck * 220 + g;
  for (int mu = 0; mu < 11; ++mu) {
    float re = 0.f, im = 0.f;
#pragma unroll
    for (int a = 0; a < 20; ++a) {
      float2 e = gF20[mu*20 + a];
      re += ya[a] * e.x; im += ya[a] * e.y;
    }
    gU[ub + mu*20] = make_float2(re, im);
  }
}

// ymn[b,c,k,mu,nu] = sum_g u[b,c,k,mu,g] * F20[nu,g]
__global__ void k_ymn() {
  int idx = blockIdx.x * blockDim.x + threadIdx.x;
  if (idx >= NB*FF1*NA1*MM2) return;
  long ub = (long)idx * 20;
  float2 ug[20];
#pragma unroll
  for (int g = 0; g < 20; ++g) ug[g] = gU[ub + g];
  long yb = (long)idx * 11;
  for (int nu = 0; nu < 11; ++nu) {
    float re = 0.f, im = 0.f;
#pragma unroll
    for (int g = 0; g < 20; ++g) {
      float2 e = gF20[nu*20 + g];
      re += ug[g].x * e.x - ug[g].y * e.y;
      im += ug[g].x * e.y + ug[g].y * e.x;
    }
    gYMN[yb + nu] = make_float2(re, im);
  }
}

// X2[b,c,l,mu,nu] = sum_k WSO3[k,l,mu,nu] * ymn[b,c,k,mu,nu]
__global__ void k_x2() {
  int idx = blockIdx.x * blockDim.x + threadIdx.x;
  if (idx >= NB*FF1*BB2*121) return;
  int mn = idx % 121, l = (idx / 121) % 6, c = (idx / 726) % 20, b = idx / 14520;
  float re = 0.f, im = 0.f;
#pragma unroll
  for (int k = 0; k < 20; ++k) {
    float w = gWSO3[(k*6 + l)*121 + mn];
    float2 v = gYMN[((b*20 + c)*20 + k)*121 + mn];
    re += w * v.x; im += w * v.y;
  }
  gX2[idx] = make_float2(re, im);
}

// psi2[i,o,l,n,k] = sum_p kernel2[i,o,p] * BSO3[p,l,n,k]
__global__ void k_psi2(const float* __restrict__ k2) {
  int idx = blockIdx.x * blockDim.x + threadIdx.x;
  if (idx >= FF1*FF2*BB2*121) return;
  int nk = idx % 121, l = (idx / 121) % 6, o = (idx / 726) % 40, i = idx / 29040;
  float re = 0.f, im = 0.f;
  const float* kr = &k2[(i*40 + o)*144];
  for (int p = 0; p < P2; ++p) {
    float kv = kr[p];
    float2 bv = gBSO3[(p*6 + l)*121 + nk];
    re += kv * bv.x; im += kv * bv.y;
  }
  gPSI2[idx] = make_float2(re, im);
}

// Z2[b,o,l,m,n] = sum_{i,k} X2[b,i,l,m,k] * conj(psi2[i,o,l,n,k]) — per-l complex GEMM
__global__ void k_z2() {
  const int R = NB * 11;     // 1408 rows (b,m)
  const int C = FF2 * 11;    // 440 cols (o,n)
  const int K = FF1 * 11;    // 220 reduction (i,k)
  int l = blockIdx.z;
  __shared__ float2 As[16][16];
  __shared__ float2 Bs[16][16];
  int row = blockIdx.y * 16 + threadIdx.y;
  int col = blockIdx.x * 16 + threadIdx.x;
  float re = 0.f, im = 0.f;
  for (int kt = 0; kt < K; kt += 16) {
    int at = kt + threadIdx.x;
    float2 av = make_float2(0.f, 0.f);
    if (row < R && at < K) {
      int b = row / 11, m = row % 11, i = at / 11, kk = at % 11;
      av = gX2[((b*FF1 + i)*BB2 + l)*121 + m*11 + kk];
    }
    As[threadIdx.y][threadIdx.x] = av;
    int bc = blockIdx.x * 16 + threadIdx.y;
    float2 bv = make_float2(0.f, 0.f);
    if (bc < C && at < K) {
      int o = bc / 11, n = bc % 11, i = at / 11, kk = at % 11;
      bv = gPSI2[((i*FF2 + o)*BB2 + l)*121 + n*11 + kk];
    }
    Bs[threadIdx.y][threadIdx.x] = bv;
    __syncthreads();
#pragma unroll
    for (int q = 0; q < 16; ++q) {
      float2 a = As[threadIdx.y][q], bq = Bs[threadIdx.x][q];
      re += a.x * bq.x + a.y * bq.y;   // a * conj(b)
      im += a.y * bq.x - a.x * bq.y;
    }
    __syncthreads();
  }
  if (row < R && col < C) {
    int b = row / 11, m = row % 11, o = col / 11, n = col % 11;
    gZ2[((b*FF2 + o)*BB2 + l)*121 + m*11 + n] = make_float2(re, im);
  }
}

// fh2[b,o,k,m,n] = sum_l WINV2[k,l,m,n] * Z2[b,o,l,m,n]
__global__ void k_fh2() {
  int idx = blockIdx.x * blockDim.x + threadIdx.x;
  if (idx >= NB*FF2*NA2*121) return;
  int mn = idx % 121, k = (idx / 121) % 12, o = (idx / 1452) % 40, b = idx / 58080;
  float re = 0.f, im = 0.f;
#pragma unroll
  for (int l = 0; l < BB2; ++l) {
    float w = gWINV2[(k*6 + l)*121 + mn];
    float2 z = gZ2[((b*FF2 + o)*BB2 + l)*121 + mn];
    re += w * z.x; im += w * z.y;
  }
  gFH2[idx] = make_float2(re, im);
}

// t2[b,o,k,m,g] = sum_n fh2[b,o,k,m,n] * EA2[n,g]
__global__ void k_t2() {
  int idx = blockIdx.x * blockDim.x + threadIdx.x;
  if (idx >= NB*FF2*NA2*MM2) return;
  long fb = (long)idx * 11;
  float2 f[11];
#pragma unroll
  for (int n = 0; n < 11; ++n) f[n] = gFH2[fb + n];
  long tb = (long)idx * 12;
  for (int g = 0; g < 12; ++g) {
    float re = 0.f, im = 0.f;
#pragma unroll
    for (int n = 0; n < 11; ++n) {
      float2 e = gEA2[n*12 + g];
      re += f[n].x * e.x - f[n].y * e.y;
      im += f[n].x * e.y + f[n].y * e.x;
    }
    gT2[tb + g] = make_float2(re, im);
  }
}

// y2[b,o,k,a,g] = relu(Re(sum_m t2[b,o,k,m,g] * EA2[m,a]))
__global__ void k_y2k() {
  int idx = blockIdx.x * blockDim.x + threadIdx.x;
  if (idx >= NB*FF2*NA2*NA2) return;
  int g = idx % 12, bok = idx / 12;
  long tbase = (long)bok * 132 + g;
  float2 tm[11];
#pragma unroll
  for (int m = 0; m < 11; ++m) tm[m] = gT2[tbase + m*12];
  long yb = (long)bok * 144 + g;
  for (int a = 0; a < 12; ++a) {
    float v = 0.f;
#pragma unroll
    for (int m = 0; m < 11; ++m) {
      float2 e = gEA2[m*12 + a];
      v += tm[m].x * e.x - tm[m].y * e.y;
    }
    gY2[yb + a*12] = (v > 0.f) ? v : 0.f;
  }
}

// feat[b,o] = sum_{k,a,g} y2 * WINT[k] / 144  (one warp per (b,o))
__global__ void k_feat() {
  int gwid = (blockIdx.x * blockDim.x + threadIdx.x) / 32;
  int lane = threadIdx.x % 32;
  if (gwid >= NB*FF2) return;
  long base = (long)gwid * 1728;
  float s = 0.f;
  for (int e = lane; e < 1728; e += 32)
    s += gY2[base + e] * gWINT[e / 144];
  for (int off = 16; off; off >>= 1) s += __shfl_down_sync(0xffffffffu, s, off);
  if (lane == 0) gFEAT[gwid] = s / 144.0f;
}

// out[b,f] = sum_o feat[b,o] * w_lin[f,o] + b_lin[f]
__global__ void k_out(const float* __restrict__ wl, const float* __restrict__ bl,
                      float* __restrict__ out) {
  int idx = blockIdx.x * blockDim.x + threadIdx.x;
  if (idx >= NB*FOUT) return;
  int f = idx % FOUT, b = idx / FOUT;
  float acc = bl[f];
#pragma unroll
  for (int o = 0; o < FF2; ++o) acc += gFEAT[b*FF2 + o] * wl[f*FF2 + o];
  out[idx] = acc;
}

extern "C" void kernel_launch(void* const* d_in, const int* in_sizes, int n_in,
                              void* d_out, int out_size) {
  const float* x  = (const float*)d_in[0];
  const float* k1 = (const float*)d_in[1];
  const float* k2 = (const float*)d_in[2];
  const float* wl = (const float*)d_in[3];
  const float* bl = (const float*)d_in[4];
  float* out = (float*)d_out;

  k_init_small<<<412, 256>>>();
  k_init_T1<<<(171000 + 255) / 256, 256>>>();

  k_x  <<<NB, 256>>>(x);
  k_psi<<<(FF1*BB1*MM1 + 255) / 256, 256>>>(k1);
  k_fh <<<(NB*FF1*NA1*MM1*MM1 + 255) / 256, 256>>>();
  k_t  <<<(NB*FF1*NA1*MM1 + 255) / 256, 256>>>();
  k_y  <<<(NB*FF1*NA1*NA1 + 255) / 256, 256>>>();
  k_u  <<<(NB*FF1*NA1*NA1 + 255) / 256, 256>>>();
  k_ymn<<<(NB*FF1*NA1*MM2 + 255) / 256, 256>>>();
  k_x2 <<<(NB*FF1*BB2*121 + 255) / 256, 256>>>();
  k_psi2<<<(FF1*FF2*BB2*121 + 255) / 256, 256>>>(k2);
  {
    dim3 g((FF2*11 + 15) / 16, (NB*11) / 16, BB2);
    k_z2<<<g, dim3(16, 16)>>>();
  }
  k_fh2<<<(NB*FF2*NA2*121 + 255) / 256, 256>>>();
  k_t2 <<<(NB*FF2*NA2*MM2 + 255) / 256, 256>>>();
  k_y2k<<<(NB*FF2*NA2*NA2 + 255) / 256, 256>>>();
  k_feat<<<(NB*FF2*32 + 127) / 128, 128>>>();
  k_out<<<(NB*FOUT + 255) / 256, 256>>>(wl, bl, out);
}

// round 2
// speedup vs baseline: 2.0170x; 2.0170x over previous
#include <cuda_runtime.h>
#include <math.h>

#define DPI 3.14159265358979323846

// ---- problem dims ----
#define NB   128
#define NIN  30     // 2*B_IN
#define BB1  10
#define MM1  19     // 2*B1-1
#define NA1  20     // 2*B1
#define FF1  20
#define BB2  6
#define MM2  11     // 2*B2-1
#define NA2  12     // 2*B2
#define FF2  40
#define FOUT 10
#define P1   24
#define P2   144

// ---- constant tables (rebuilt on device every call) ----
__device__ float  gWS2F[BB1*MM1*NIN];              // [l][m][k]
__device__ float2 gT1t[NIN*NIN*BB1*MM1];           // [k*30+j][lm]  (transposed)
__device__ float2 gBS2[P1*BB1*MM1];                // [p][l][m]
__device__ float  gWINV1[NA1*BB1*MM1*MM1];         // [k][l][m][n]
__device__ float2 gEA1[MM1*NA1];                   // [m][a]  exp(+i(m-9)*2pi*a/20)
__device__ float  gWSO3[NA1*BB2*MM2*MM2];          // [k][l][m][n]
__device__ float2 gF20[MM2*NA1];                   // [mu][a] exp(-2pi i (mu-5) a /20)
__device__ float2 gBSO3[P2*BB2*MM2*MM2];           // [p][l][m][n]
__device__ float  gWINV2[NA2*BB2*MM2*MM2];         // [k][l][m][n]
__device__ float2 gEA2[MM2*NA2];                   // [m][a]  exp(+i(m-5)*2pi*a/12)
__device__ float  gWINT[NA2];

// ---- scratch ----
__device__ float2 gX   [NB*BB1*MM1];
__device__ float2 gPSI [FF1*BB1*MM1];
__device__ float2 gFH  [NB*FF1*NA1*MM1*MM1];       // 18,483,200
__device__ float2 gT   [NB*FF1*NA1*MM1*NA1];       // 19,456,000
__device__ float  gY   [NB*FF1*NA1*NA1*NA1];       // 20,480,000
__device__ float2 gU   [NB*FF1*NA1*MM2*NA1];       // 11,264,000
__device__ float2 gYMN [NB*FF1*NA1*MM2*MM2];       //  6,195,200
__device__ float2 gX2  [NB*FF1*BB2*MM2*MM2];       //  1,858,560
__device__ float2 gPSI2[FF1*FF2*BB2*MM2*MM2];      //    580,800
__device__ float2 gZ2  [NB*FF2*BB2*MM2*MM2];       //  3,717,120
__device__ float2 gFH2 [NB*FF2*NA2*MM2*MM2];       //  7,434,240
__device__ float2 gT2  [NB*FF2*NA2*MM2*NA2];       //  8,110,080
__device__ float  gY2  [NB*FF2*NA2*NA2*NA2];       //  8,847,360
__device__ float  gFEAT[NB*FF2];

// ---- exact factorials 0..20 ----
__device__ __constant__ double c_fact[21] = {
  1.0, 1.0, 2.0, 6.0, 24.0, 120.0, 720.0, 5040.0, 40320.0, 362880.0,
  3628800.0, 39916800.0, 479001600.0, 6227020800.0, 87178291200.0,
  1307674368000.0, 20922789888000.0, 355687428096000.0,
  6402373705728000.0, 121645100408832000.0, 2432902008176640000.0 };

__device__ __forceinline__ double ipowd(double x, int e) {
  double r = 1.0;
  for (int i = 0; i < e; ++i) r *= x;
  return r;
}

__device__ double wigd(int l, int m, int n, double beta) {
  double cb = cos(0.5 * beta), sb = sin(0.5 * beta);
  double pref = sqrt(c_fact[l+m] * c_fact[l-m] * c_fact[l+n] * c_fact[l-n]);
  int s0 = (n - m > 0) ? (n - m) : 0;
  int s1 = (l + n < l - m) ? (l + n) : (l - m);
  double v = 0.0;
  for (int s = s0; s <= s1; ++s) {
    double t = 1.0 / (c_fact[l+n-s] * c_fact[s] * c_fact[m-n+s] * c_fact[l-m-s]);
    if ((m - n + s) & 1) t = -t;
    v += t * ipowd(cb, 2*l + n - m - 2*s) * ipowd(sb, m - n + 2*s);
  }
  return pref * v;
}

__device__ double quadw(int b, int k) {
  double beta = DPI * (2*k + 1) / (4.0 * b);
  double s = 0.0;
  for (int j = 0; j < b; ++j) s += sin((2*j + 1) * beta) / (2*j + 1);
  return 2.0 / b * sin(beta) * s;
}

// ======================= init kernels =======================
__global__ void k_init_small() {
  const int TOT = 5700 + 4560 + 72200 + 380 + 14520 + 220 + 104544 + 8712 + 132 + 12;
  for (int idx = blockIdx.x * blockDim.x + threadIdx.x; idx < TOT;
       idx += gridDim.x * blockDim.x) {
    int r = idx;
    if (r < 5700) {  // WS2F [l][m][k]
      int l = r / 570, m = (r / 30) % 19, k = r % 30;
      int mp = m - 9;
      double w = 0.0;
      if (abs(mp) <= l) {
        double beta = DPI * (2*k + 1) / 60.0;
        w = wigd(l, mp, 0, beta) * quadw(15, k);
      }
      gWS2F[r] = (float)w; continue;
    }
    r -= 5700;
    if (r < 4560) {  // BS2 [p][l][m]
      int p = r / 190, l = (r / 19) % 10, m = r % 19, mp = m - 9;
      float2 v = make_float2(0.f, 0.f);
      if (abs(mp) <= l) {
        int ib = p / 8, ia = p % 8;
        double beta = (ib + 1) * DPI / 24.0;
        double d = wigd(l, mp, 0, beta);
        double ph = -(double)mp * (2.0 * DPI * ia / 8.0);
        double s, c; sincos(ph, &s, &c);
        v = make_float2((float)(d * c), (float)(d * s));
      }
      gBS2[r] = v; continue;
    }
    r -= 4560;
    if (r < 72200) {  // WINV1 [k][l][m][n]
      int k = r / 3610, l = (r / 361) % 10, m = (r / 19) % 19, n = r % 19;
      int mp = m - 9, np = n - 9;
      double w = 0.0;
      if (abs(mp) <= l && abs(np) <= l) {
        double beta = DPI * (2*k + 1) / 40.0;
        w = wigd(l, mp, np, beta) * (2*l + 1);
      }
      gWINV1[r] = (float)w; continue;
    }
    r -= 72200;
    if (r < 380) {  // EA1 [m][a]
      int m = r / 20, a = r % 20;
      double ph = (double)(m - 9) * 2.0 * DPI * a / 20.0;
      double s, c; sincos(ph, &s, &c);
      gEA1[r] = make_float2((float)c, (float)s); continue;
    }
    r -= 380;
    if (r < 14520) {  // WSO3 [k][l][m][n]
      int k = r / 726, l = (r / 121) % 6, m = (r / 11) % 11, n = r % 11;
      int mp = m - 5, np = n - 5;
      double w = 0.0;
      if (abs(mp) <= l && abs(np) <= l) {
        double beta = DPI * (2*k + 1) / 40.0;
        w = wigd(l, mp, np, beta) * quadw(10, k);
      }
      gWSO3[r] = (float)w; continue;
    }
    r -= 14520;
    if (r < 220) {  // F20 [mu][a]
      int mu = r / 20, a = r % 20;
      double ph = -2.0 * DPI * (double)(mu - 5) * a / 20.0;
      double s, c; sincos(ph, &s, &c);
      gF20[r] = make_float2((float)c, (float)s); continue;
    }
    r -= 220;
    if (r < 104544) {  // BSO3 [p][l][m][n]
      int p = r / 726, l = (r / 121) % 6, m = (r / 11) % 11, n = r % 11;
      int mp = m - 5, np = n - 5;
      float2 v = make_float2(0.f, 0.f);
      if (abs(mp) <= l && abs(np) <= l) {
        int ib = p / 48, ia = (p / 6) % 8, ig = p % 6;
        double beta = (ib + 1) * DPI / 24.0;
        double d = wigd(l, mp, np, beta);
        double ph = -((double)mp * (2.0 * DPI * ia / 8.0) +
                      (double)np * (2.0 * DPI * ig / 6.0));
        double s, c; sincos(ph, &s, &c);
        v = make_float2((float)(d * c), (float)(d * s));
      }
      gBSO3[r] = v; continue;
    }
    r -= 104544;
    if (r < 8712) {  // WINV2 [k][l][m][n]
      int k = r / 726, l = (r / 121) % 6, m = (r / 11) % 11, n = r % 11;
      int mp = m - 5, np = n - 5;
      double w = 0.0;
      if (abs(mp) <= l && abs(np) <= l) {
        double beta = DPI * (2*k + 1) / 24.0;
        w = wigd(l, mp, np, beta) * (2*l + 1);
      }
      gWINV2[r] = (float)w; continue;
    }
    r -= 8712;
    if (r < 132) {  // EA2 [m][a]
      int m = r / 12, a = r % 12;
      double ph = (double)(m - 5) * 2.0 * DPI * a / 12.0;
      double s, c; sincos(ph, &s, &c);
      gEA2[r] = make_float2((float)c, (float)s); continue;
    }
    r -= 132;
    gWINT[r] = (float)quadw(6, r);
  }
}

// T1t[(k*30+j)][lm] = WS2F[lm][k] * exp(-2pi i (m-9) j /30)   (transposed layout)
__global__ void k_init_T1() {
  int idx = blockIdx.x * blockDim.x + threadIdx.x;
  if (idx >= BB1*MM1*900) return;
  int lm = idx / 900, kj = idx % 900;
  int k = kj / 30, j = kj % 30;
  int mp = (lm % 19) - 9;
  float w = gWS2F[lm * 30 + k];
  double ph = -2.0 * DPI * (double)mp * j / 30.0;
  double s, c; sincos(ph, &s, &c);
  gT1t[kj * 190 + lm] = make_float2((float)(w * c), (float)(w * s));
}

// ======================= pipeline kernels =======================
// X[b,lm] = sum_{kj} T1t[kj][lm] * x[b,kj]   (coalesced over lm)
__global__ void k_x(const float* __restrict__ x) {
  __shared__ float xs[900];
  int b = blockIdx.x;
  for (int i = threadIdx.x; i < 900; i += blockDim.x) xs[i] = x[b*900 + i];
  __syncthreads();
  int t = threadIdx.x;
  if (t < BB1*MM1) {
    float re = 0.f, im = 0.f;
#pragma unroll 4
    for (int i = 0; i < 900; ++i) {
      float xv = xs[i];
      float2 w = gT1t[i * 190 + t];
      re += xv * w.x; im += xv * w.y;
    }
    gX[b * 190 + t] = make_float2(re, im);
  }
}

// psi[o,l,m] = sum_p kernel1[o,p] * BS2[p,l,m]
__global__ void k_psi(const float* __restrict__ k1) {
  int idx = blockIdx.x * blockDim.x + threadIdx.x;
  if (idx >= FF1*BB1*MM1) return;
  int lm = idx % 190, o = idx / 190;
  float re = 0.f, im = 0.f;
  for (int p = 0; p < P1; ++p) {
    float kv = k1[o*P1 + p];
    float2 bv = gBS2[p*190 + lm];
    re += kv * bv.x; im += kv * bv.y;
  }
  gPSI[idx] = make_float2(re, im);
}

// fh[b,o,k,m,n] = sum_l WINV1[k,l,m,n] * X[b,l,m] * conj(psi[o,l,n])
__global__ void k_fh() {
  int idx = blockIdx.x * blockDim.x + threadIdx.x;
  if (idx >= NB*FF1*NA1*MM1*MM1) return;
  int n = idx % 19, m = (idx / 19) % 19, k = (idx / 361) % 20;
  int o = (idx / 7220) % 20, b = idx / 144400;
  float re = 0.f, im = 0.f;
#pragma unroll
  for (int l = 0; l < BB1; ++l) {
    float w = gWINV1[(k*BB1 + l)*361 + m*19 + n];
    float2 xm = gX[(b*BB1 + l)*19 + m];
    float2 pe = gPSI[(o*BB1 + l)*19 + n];
    re += w * (xm.x * pe.x + xm.y * pe.y);
    im += w * (xm.y * pe.x - xm.x * pe.y);
  }
  gFH[idx] = make_float2(re, im);
}

// t[b,o,k,m,g] = sum_n fh[b,o,k,m,n] * EA1[n,g]
__global__ void k_t() {
  int idx = blockIdx.x * blockDim.x + threadIdx.x;
  if (idx >= NB*FF1*NA1*MM1) return;
  long base = (long)idx * 19;
  float2 f[19];
#pragma unroll
  for (int n = 0; n < 19; ++n) f[n] = gFH[base + n];
  long tb = (long)idx * 20;
  for (int g = 0; g < 20; ++g) {
    float re = 0.f, im = 0.f;
#pragma unroll
    for (int n = 0; n < 19; ++n) {
      float2 e = gEA1[n*20 + g];
      re += f[n].x * e.x - f[n].y * e.y;
      im += f[n].x * e.y + f[n].y * e.x;
    }
    gT[tb + g] = make_float2(re, im);
  }
}

// y[b,o,k,a,g] = relu(Re(sum_m t[b,o,k,m,g] * EA1[m,a]))
__global__ void k_y() {
  int idx = blockIdx.x * blockDim.x + threadIdx.x;
  if (idx >= NB*FF1*NA1*NA1) return;
  int g = idx % 20, bok = idx / 20;
  long tbase = (long)bok * 380 + g;
  float2 tm[19];
#pragma unroll
  for (int m = 0; m < 19; ++m) tm[m] = gT[tbase + m*20];
  long yb = (long)bok * 400 + g;
  for (int a = 0; a < 20; ++a) {
    float v = 0.f;
#pragma unroll
    for (int m = 0; m < 19; ++m) {
      float2 e = gEA1[m*20 + a];
      v += tm[m].x * e.x - tm[m].y * e.y;
    }
    gY[yb + a*20] = (v > 0.f) ? v : 0.f;
  }
}

// u[b,c,k,mu,g] = sum_a y[b,c,k,a,g] * F20[mu,a]
__global__ void k_u() {
  int idx = blockIdx.x * blockDim.x + threadIdx.x;
  if (idx >= NB*FF1*NA1*NA1) return;
  int g = idx % 20, bck = idx / 20;
  long ybase = (long)bck * 400 + g;
  float ya[20];
#pragma unroll
  for (int a = 0; a < 20; ++a) ya[a] = gY[ybase + a*20];
  long ub = (long)bck * 220 + g;
  for (int mu = 0; mu < 11; ++mu) {
    float re = 0.f, im = 0.f;
#pragma unroll
    for (int a = 0; a < 20; ++a) {
      float2 e = gF20[mu*20 + a];
      re += ya[a] * e.x; im += ya[a] * e.y;
    }
    gU[ub + mu*20] = make_float2(re, im);
  }
}

// ymn[b,c,k,mu,nu] = sum_g u[b,c,k,mu,g] * F20[nu,g]
__global__ void k_ymn() {
  int idx = blockIdx.x * blockDim.x + threadIdx.x;
  if (idx >= NB*FF1*NA1*MM2) return;
  long ub = (long)idx * 20;
  float2 ug[20];
#pragma unroll
  for (int g = 0; g < 20; ++g) ug[g] = gU[ub + g];
  long yb = (long)idx * 11;
  for (int nu = 0; nu < 11; ++nu) {
    float re = 0.f, im = 0.f;
#pragma unroll
    for (int g = 0; g < 20; ++g) {
      float2 e = gF20[nu*20 + g];
      re += ug[g].x * e.x - ug[g].y * e.y;
      im += ug[g].x * e.y + ug[g].y * e.x;
    }
    gYMN[yb + nu] = make_float2(re, im);
  }
}

// X2[b,c,l,mu,nu] = sum_k WSO3[k,l,mu,nu] * ymn[b,c,k,mu,nu]
__global__ void k_x2() {
  int idx = blockIdx.x * blockDim.x + threadIdx.x;
  if (idx >= NB*FF1*BB2*121) return;
  int mn = idx % 121, l = (idx / 121) % 6, c = (idx / 726) % 20, b = idx / 14520;
  float re = 0.f, im = 0.f;
#pragma unroll
  for (int k = 0; k < 20; ++k) {
    float w = gWSO3[(k*6 + l)*121 + mn];
    float2 v = gYMN[((b*20 + c)*20 + k)*121 + mn];
    re += w * v.x; im += w * v.y;
  }
  gX2[idx] = make_float2(re, im);
}

// psi2[i,o,l,n,k] = sum_p kernel2[i,o,p] * BSO3[p,l,n,k]
__global__ void k_psi2(const float* __restrict__ k2) {
  int idx = blockIdx.x * blockDim.x + threadIdx.x;
  if (idx >= FF1*FF2*BB2*121) return;
  int nk = idx % 121, l = (idx / 121) % 6, o = (idx / 726) % 40, i = idx / 29040;
  float re = 0.f, im = 0.f;
  const float* kr = &k2[(i*40 + o)*144];
  for (int p = 0; p < P2; ++p) {
    float kv = kr[p];
    float2 bv = gBSO3[(p*6 + l)*121 + nk];
    re += kv * bv.x; im += kv * bv.y;
  }
  gPSI2[idx] = make_float2(re, im);
}

// Z2[b,o,l,m,n] = sum_{i,k} X2[b,i,l,m,k] * conj(psi2[i,o,l,n,k])
// Complex GEMM per l: (1408 x 220) x (220 x 440), 32x32 tile, 2x2 register tiling,
// K-major padded B tile (conflict-free float4 reads), broadcast A reads.
__global__ void k_z2() {
  const int R = NB * 11;     // 1408
  const int C = FF2 * 11;    // 440
  const int K = FF1 * 11;    // 220
  int l = blockIdx.z;
  __shared__ __align__(16) float2 As[32][17];
  __shared__ __align__(16) float2 Bs[16][34];
  int tx = threadIdx.x, ty = threadIdx.y;
  int tid = ty * 16 + tx;
  int row0 = blockIdx.y * 32, col0 = blockIdx.x * 32;
  float2 c00 = {0.f,0.f}, c01 = {0.f,0.f}, c10 = {0.f,0.f}, c11 = {0.f,0.f};

  for (int kt = 0; kt < K; kt += 16) {
#pragma unroll
    for (int e = tid; e < 512; e += 256) {   // As: [i][kq]
      int i = e >> 4, kq = e & 15;
      int kc = kt + kq;
      float2 v = make_float2(0.f, 0.f);
      if (kc < K) {
        int row = row0 + i;
        int b = row / 11, m = row % 11, ii = kc / 11, kk = kc % 11;
        v = gX2[((b*FF1 + ii)*BB2 + l)*121 + m*11 + kk];
      }
      As[i][kq] = v;
    }
#pragma unroll
    for (int e = tid; e < 512; e += 256) {   // Bs: [kq][j]
      int kq = e >> 5, j = e & 31;
      int kc = kt + kq, col = col0 + j;
      float2 v = make_float2(0.f, 0.f);
      if (kc < K && col < C) {
        int o = col / 11, n = col % 11, ii = kc / 11, kk = kc % 11;
        v = gPSI2[((ii*FF2 + o)*BB2 + l)*121 + n*11 + kk];
      }
      Bs[kq][j] = v;
    }
    __syncthreads();
#pragma unroll
    for (int kq = 0; kq < 16; ++kq) {
      float2 a0 = As[ty*2][kq];
      float2 a1 = As[ty*2 + 1][kq];
      float4 bb = *reinterpret_cast<const float4*>(&Bs[kq][tx*2]);
      // acc += a * conj(b)
      c00.x += a0.x*bb.x + a0.y*bb.y;  c00.y += a0.y*bb.x - a0.x*bb.y;
      c01.x += a0.x*bb.z + a0.y*bb.w;  c01.y += a0.y*bb.z - a0.x*bb.w;
      c10.x += a1.x*bb.x + a1.y*bb.y;  c10.y += a1.y*bb.x - a1.x*bb.y;
      c11.x += a1.x*bb.z + a1.y*bb.w;  c11.y += a1.y*bb.z - a1.x*bb.w;
    }
    __syncthreads();
  }

  int r0 = row0 + ty*2, cc0 = col0 + tx*2;
  {
    int b = r0 / 11, m = r0 % 11;
    int b1 = (r0+1) / 11, m1 = (r0+1) % 11;
    if (cc0 < C) {
      int o = cc0 / 11, n = cc0 % 11;
      gZ2[((b*FF2 + o)*BB2 + l)*121 + m*11 + n] = c00;
      gZ2[((b1*FF2 + o)*BB2 + l)*121 + m1*11 + n] = c10;
    }
    if (cc0 + 1 < C) {
      int o = (cc0+1) / 11, n = (cc0+1) % 11;
      gZ2[((b*FF2 + o)*BB2 + l)*121 + m*11 + n] = c01;
      gZ2[((b1*FF2 + o)*BB2 + l)*121 + m1*11 + n] = c11;
    }
  }
}

// fh2[b,o,k,m,n] = sum_l WINV2[k,l,m,n] * Z2[b,o,l,m,n]
__global__ void k_fh2() {
  int idx = blockIdx.x * blockDim.x + threadIdx.x;
  if (idx >= NB*FF2*NA2*121) return;
  int mn = idx % 121, k = (idx / 121) % 12, o = (idx / 1452) % 40, b = idx / 58080;
  float re = 0.f, im = 0.f;
#pragma unroll
  for (int l = 0; l < BB2; ++l) {
    float w = gWINV2[(k*6 + l)*121 + mn];
    float2 z = gZ2[((b*FF2 + o)*BB2 + l)*121 + mn];
    re += w * z.x; im += w * z.y;
  }
  gFH2[idx] = make_float2(re, im);
}

// t2[b,o,k,m,g] = sum_n fh2[b,o,k,m,n] * EA2[n,g]
__global__ void k_t2() {
  int idx = blockIdx.x * blockDim.x + threadIdx.x;
  if (idx >= NB*FF2*NA2*MM2) return;
  long fb = (long)idx * 11;
  float2 f[11];
#pragma unroll
  for (int n = 0; n < 11; ++n) f[n] = gFH2[fb + n];
  long tb = (long)idx * 12;
  for (int g = 0; g < 12; ++g) {
    float re = 0.f, im = 0.f;
#pragma unroll
    for (int n = 0; n < 11; ++n) {
      float2 e = gEA2[n*12 + g];
      re += f[n].x * e.x - f[n].y * e.y;
      im += f[n].x * e.y + f[n].y * e.x;
    }
    gT2[tb + g] = make_float2(re, im);
  }
}

// y2[b,o,k,a,g] = relu(Re(sum_m t2[b,o,k,m,g] * EA2[m,a]))
__global__ void k_y2k() {
  int idx = blockIdx.x * blockDim.x + threadIdx.x;
  if (idx >= NB*FF2*NA2*NA2) return;
  int g = idx % 12, bok = idx / 12;
  long tbase = (long)bok * 132 + g;
  float2 tm[11];
#pragma unroll
  for (int m = 0; m < 11; ++m) tm[m] = gT2[tbase + m*12];
  long yb = (long)bok * 144 + g;
  for (int a = 0; a < 12; ++a) {
    float v = 0.f;
#pragma unroll
    for (int m = 0; m < 11; ++m) {
      float2 e = gEA2[m*12 + a];
      v += tm[m].x * e.x - tm[m].y * e.y;
    }
    gY2[yb + a*12] = (v > 0.f) ? v : 0.f;
  }
}

// feat[b,o] = sum_{k,a,g} y2 * WINT[k] / 144
__global__ void k_feat() {
  int gwid = (blockIdx.x * blockDim.x + threadIdx.x) / 32;
  int lane = threadIdx.x % 32;
  if (gwid >= NB*FF2) return;
  long base = (long)gwid * 1728;
  float s = 0.f;
  for (int e = lane; e < 1728; e += 32)
    s += gY2[base + e] * gWINT[e / 144];
  for (int off = 16; off; off >>= 1) s += __shfl_down_sync(0xffffffffu, s, off);
  if (lane == 0) gFEAT[gwid] = s / 144.0f;
}

// out[b,f] = sum_o feat[b,o] * w_lin[f,o] + b_lin[f]
__global__ void k_out(const float* __restrict__ wl, const float* __restrict__ bl,
                      float* __restrict__ out) {
  int idx = blockIdx.x * blockDim.x + threadIdx.x;
  if (idx >= NB*FOUT) return;
  int f = idx % FOUT, b = idx / FOUT;
  float acc = bl[f];
#pragma unroll
  for (int o = 0; o < FF2; ++o) acc += gFEAT[b*FF2 + o] * wl[f*FF2 + o];
  out[idx] = acc;
}

extern "C" void kernel_launch(void* const* d_in, const int* in_sizes, int n_in,
                              void* d_out, int out_size) {
  const float* x  = (const float*)d_in[0];
  const float* k1 = (const float*)d_in[1];
  const float* k2 = (const float*)d_in[2];
  const float* wl = (const float*)d_in[3];
  const float* bl = (const float*)d_in[4];
  float* out = (float*)d_out;

  k_init_small<<<412, 256>>>();
  k_init_T1<<<(171000 + 255) / 256, 256>>>();

  k_x  <<<NB, 192>>>(x);
  k_psi<<<(FF1*BB1*MM1 + 255) / 256, 256>>>(k1);
  k_fh <<<(NB*FF1*NA1*MM1*MM1 + 255) / 256, 256>>>();
  k_t  <<<(NB*FF1*NA1*MM1 + 255) / 256, 256>>>();
  k_y  <<<(NB*FF1*NA1*NA1 + 255) / 256, 256>>>();
  k_u  <<<(NB*FF1*NA1*NA1 + 255) / 256, 256>>>();
  k_ymn<<<(NB*FF1*NA1*MM2 + 255) / 256, 256>>>();
  k_x2 <<<(NB*FF1*BB2*121 + 255) / 256, 256>>>();
  k_psi2<<<(FF1*FF2*BB2*121 + 255) / 256, 256>>>(k2);
  {
    dim3 g((FF2*11 + 31) / 32, (NB*11) / 32, BB2);
    k_z2<<<g, dim3(16, 16)>>>();
  }
  k_fh2<<<(NB*FF2*NA2*121 + 255) / 256, 256>>>();
  k_t2 <<<(NB*FF2*NA2*MM2 + 255) / 256, 256>>>();
  k_y2k<<<(NB*FF2*NA2*NA2 + 255) / 256, 256>>>();
  k_feat<<<(NB*FF2*32 + 127) / 128, 128>>>();
  k_out<<<(NB*FOUT + 255) / 256, 256>>>(wl, bl, out);
}